// round 1
// baseline (speedup 1.0000x reference)
#include <cuda_runtime.h>
#include <cuda_fp16.h>

#define T_STEPS 8192
#define HDIM    1024
#define IN_DIM  9
#define NC0     49
#define NC1     99
#define NCTA    (NC0 + NC1)
#define NTHR    256

// Persistent scratch (allowed: __device__ globals, no runtime allocation).
__device__ __align__(16) float g_h0[(size_t)T_STEPS * HDIM];   // layer0 hidden outputs
__device__ __align__(16) float g_h1[(size_t)T_STEPS * HDIM];   // layer1 hidden outputs
__device__ unsigned long long g_arrive;   // monotonic arrival counter (never reset)
__device__ unsigned long long g_epoch;    // monotonic release counter

// Shared memory layout (bytes). Worst-case weight slice: 44 rows * 2048 * 2B.
#define OFF_SV   180224          // float[2048]  staged v vector
#define OFF_SB   188416          // float[96]    biases
#define OFF_SG   188800          // float[96]    gate preactivations
#define OFF_SC   189184          // float[32]    cell state (persistent)
#define OFF_SX   189312          // float[16]    current x[t]
#define OFF_WIH  189376          // float[96*12] layer0 input weights (fp32)
#define SMEM_BYTES 193984

__device__ __forceinline__ float fsig(float x) {
    return __fdividef(1.0f, 1.0f + __expf(-x));
}
__device__ __forceinline__ float ftanh_(float x) {
    float a = fabsf(x);
    float e = __expf(-2.0f * a);
    float t = __fdividef(1.0f - e, 1.0f + e);
    return copysignf(t, x);
}

// Warp-per-row dot products, 2-row ILP, fp16 weights from SMEM, fp32 v in
// registers, fp32 accumulation. NIT = K/256 (K = 1024 or 2048).
template<int NIT>
__device__ __forceinline__ void compute_rows(const __half* __restrict__ sw,
                                             const float*  __restrict__ sv,
                                             const float*  __restrict__ sb,
                                             float*        __restrict__ sg,
                                             const float*  __restrict__ swih,
                                             const float*  __restrict__ sx,
                                             bool isL0, int nrows)
{
    constexpr int K = NIT * 256;
    const int wid  = threadIdx.x >> 5;
    const int lane = threadIdx.x & 31;

    // Cache this lane's v chunk in registers (covers all k for lane pattern
    // (it*32+lane)*8 .. +7), matching the weight LDS.128 chunking.
    float vr[NIT * 8];
#pragma unroll
    for (int it = 0; it < NIT; ++it) {
        const float4* p = (const float4*)(sv + (it * 32 + lane) * 8);
        float4 a = p[0], b = p[1];
        vr[it*8+0]=a.x; vr[it*8+1]=a.y; vr[it*8+2]=a.z; vr[it*8+3]=a.w;
        vr[it*8+4]=b.x; vr[it*8+5]=b.y; vr[it*8+6]=b.z; vr[it*8+7]=b.w;
    }

    for (int r0 = wid; r0 < nrows; r0 += 16) {
        const int  r1   = r0 + 8;
        const bool has1 = (r1 < nrows);
        float acc0 = 0.f, acc1 = 0.f;
        const uint4* w0 = (const uint4*)(sw + (size_t)r0 * K);
        const uint4* w1 = (const uint4*)(sw + (size_t)(has1 ? r1 : r0) * K);
#pragma unroll
        for (int it = 0; it < NIT; ++it) {
            uint4 aw = w0[it * 32 + lane];   // 8 halfs, conflict-free LDS.128
            uint4 bw = w1[it * 32 + lane];
            const __half2* ah = (const __half2*)&aw;
            const __half2* bh = (const __half2*)&bw;
#pragma unroll
            for (int q = 0; q < 4; ++q) {
                float2 fa = __half22float2(ah[q]);
                float2 fb = __half22float2(bh[q]);
                acc0 = fmaf(fa.x, vr[it*8+q*2+0], acc0);
                acc1 = fmaf(fb.x, vr[it*8+q*2+0], acc1);
                acc0 = fmaf(fa.y, vr[it*8+q*2+1], acc0);
                acc1 = fmaf(fb.y, vr[it*8+q*2+1], acc1);
            }
        }
#pragma unroll
        for (int off = 16; off; off >>= 1) {
            acc0 += __shfl_xor_sync(0xffffffffu, acc0, off);
            acc1 += __shfl_xor_sync(0xffffffffu, acc1, off);
        }
        if (lane == 0) {
            float g0 = acc0 + sb[r0];
            if (isL0) {
#pragma unroll
                for (int q = 0; q < IN_DIM; ++q) g0 = fmaf(swih[r0*12+q], sx[q], g0);
            }
            sg[r0] = g0;
            if (has1) {
                float g1 = acc1 + sb[r1];
                if (isL0) {
#pragma unroll
                    for (int q = 0; q < IN_DIM; ++q) g1 = fmaf(swih[r1*12+q], sx[q], g1);
                }
                sg[r1] = g1;
            }
        }
    }
}

__global__ void __launch_bounds__(NTHR, 1)
lstm_kernel(const float* __restrict__ x,
            const float* __restrict__ wih0, const float* __restrict__ whh0,
            const float* __restrict__ bih0, const float* __restrict__ bhh0,
            const float* __restrict__ wih1, const float* __restrict__ whh1,
            const float* __restrict__ bih1, const float* __restrict__ bhh1,
            const float* __restrict__ wlin, const float* __restrict__ blin,
            float* __restrict__ out)
{
    extern __shared__ char smem[];
    __half* sw   = (__half*)smem;
    float*  sv   = (float*)(smem + OFF_SV);
    float*  sb   = (float*)(smem + OFF_SB);
    float*  sg   = (float*)(smem + OFF_SG);
    float*  sc   = (float*)(smem + OFF_SC);
    float*  sx   = (float*)(smem + OFF_SX);
    float*  swih = (float*)(smem + OFF_WIH);

    const int  bid  = blockIdx.x;
    const int  tid  = threadIdx.x;
    const bool isL0 = (bid < NC0);
    const int  lb   = isL0 ? bid : (bid - NC0);
    const int  np   = isL0 ? NC0 : NC1;
    const int  j0   = lb * HDIM / np;
    const int  j1   = (lb + 1) * HDIM / np;
    const int  nj   = j1 - j0;
    const int  nrows = nj * 4;

    // ---- Prologue: stage this CTA's weight slice into SMEM as fp16 ----
    // Local row lr = jl*4 + gate, global row R = gate*H + j0 + jl
    // (PyTorch gate order i,f,g,o matches the reference's jnp.split).
    if (isL0) {
        const int tot = nrows << 10;
        for (int idx = tid; idx < tot; idx += NTHR) {
            int lr = idx >> 10, k = idx & 1023;
            int R = ((lr & 3) << 10) + j0 + (lr >> 2);
            sw[idx] = __float2half(whh0[((size_t)R << 10) + k]);
        }
        for (int idx = tid; idx < nrows * IN_DIM; idx += NTHR) {
            int lr = idx / IN_DIM, q = idx - lr * IN_DIM;
            int R = ((lr & 3) << 10) + j0 + (lr >> 2);
            swih[lr * 12 + q] = wih0[R * IN_DIM + q];
        }
        for (int lr = tid; lr < nrows; lr += NTHR) {
            int R = ((lr & 3) << 10) + j0 + (lr >> 2);
            sb[lr] = bih0[R] + bhh0[R];
        }
    } else {
        // Layer1 combined row: [W_ih1_row (vs h0[t]) | W_hh1_row (vs h1[t-1])]
        const int tot = nrows << 11;
        for (int idx = tid; idx < tot; idx += NTHR) {
            int lr = idx >> 11, k = idx & 2047;
            int R = ((lr & 3) << 10) + j0 + (lr >> 2);
            float w = (k < 1024) ? wih1[((size_t)R << 10) + k]
                                 : whh1[((size_t)R << 10) + (k - 1024)];
            sw[idx] = __float2half(w);
        }
        for (int lr = tid; lr < nrows; lr += NTHR) {
            int R = ((lr & 3) << 10) + j0 + (lr >> 2);
            sb[lr] = bih1[R] + bhh1[R];
        }
    }
    __syncthreads();

    // Epoch base: read before anyone can arrive at barrier 0 (release requires
    // all NCTA arrivals, each of which follows its CTA's base read).
    const unsigned long long base = *(volatile unsigned long long*)&g_epoch;

    // ---- Pipelined recurrence: epoch s -> layer0 computes t=s,
    //      layer1 computes t=s-1. One global barrier per epoch. ----
    for (int s = 0; s <= T_STEPS; ++s) {
        const bool active = isL0 ? (s < T_STEPS) : (s >= 1);
        if (active) {
            const int t = isL0 ? s : (s - 1);

            // Stage v into SMEM once per CTA (coalesced), zeros at t<=0 edges.
            if (isL0) {
                float4* d = (float4*)sv;   // 256 float4 = H
                d[tid] = (s == 0) ? make_float4(0.f, 0.f, 0.f, 0.f)
                                  : ((const float4*)(g_h0 + (size_t)(s - 1) * HDIM))[tid];
                if (tid < IN_DIM) sx[tid] = x[t * IN_DIM + tid];
            } else {
                float4* d = (float4*)sv;   // 512 float4 = [h0[t] | h1[t-1]]
                d[tid]       = ((const float4*)(g_h0 + (size_t)(s - 1) * HDIM))[tid];
                d[tid + 256] = (s == 1) ? make_float4(0.f, 0.f, 0.f, 0.f)
                                        : ((const float4*)(g_h1 + (size_t)(s - 2) * HDIM))[tid];
            }
            __syncthreads();

            if (isL0) compute_rows<4>(sw, sv, sb, sg, swih, sx, true,  nrows);
            else      compute_rows<8>(sw, sv, sb, sg, swih, sx, false, nrows);
            __syncthreads();

            // Gate nonlinearities + c/h update: one thread per owned j.
            if (tid < nj) {
                float gi = sg[tid*4+0], gf = sg[tid*4+1];
                float gc = sg[tid*4+2], go = sg[tid*4+3];
                float i_ = fsig(gi), f_ = fsig(gf);
                float ci = ftanh_(gc), o_ = fsig(go);
                float cp = (t == 0) ? 0.f : sc[tid];
                float c  = fmaf(f_, cp, i_ * ci);
                sc[tid] = c;
                float h = o_ * ftanh_(c);
                float* dst = isL0 ? (g_h0 + (size_t)s * HDIM)
                                  : (g_h1 + (size_t)t * HDIM);
                dst[j0 + tid] = h;
            }
        }

        // ---- Grid barrier (monotonic counters, replay-safe, no resets) ----
        __syncthreads();
        if (tid == 0) {
            __threadfence();
            const unsigned long long target = base + (unsigned long long)(s + 1);
            unsigned long long old = atomicAdd(&g_arrive, 1ULL);
            if (old + 1ULL == target * (unsigned long long)NCTA) {
                atomicExch(&g_epoch, target);                 // release
            } else {
                while (*(volatile unsigned long long*)&g_epoch < target) { }
            }
            __threadfence();
        }
        __syncthreads();
    }

    // ---- Final linear: out = h1[T-1] . w_lin + b_lin (CTA 0) ----
    if (bid == 0) {
        const float* hl = g_h1 + (size_t)(T_STEPS - 1) * HDIM;
        float p = 0.f;
        for (int k = tid; k < HDIM; k += NTHR) p = fmaf(hl[k], wlin[k], p);
#pragma unroll
        for (int off = 16; off; off >>= 1) p += __shfl_xor_sync(0xffffffffu, p, off);
        if ((tid & 31) == 0) sv[tid >> 5] = p;
        __syncthreads();
        if (tid == 0) {
            float sres = blin[0];
            for (int w = 0; w < 8; ++w) sres += sv[w];
            out[0] = sres;
        }
    }
}

extern "C" void kernel_launch(void* const* d_in, const int* in_sizes, int n_in,
                              void* d_out, int out_size)
{
    cudaFuncSetAttribute(lstm_kernel,
                         cudaFuncAttributeMaxDynamicSharedMemorySize, SMEM_BYTES);
    lstm_kernel<<<NCTA, NTHR, SMEM_BYTES>>>(
        (const float*)d_in[0],
        (const float*)d_in[1], (const float*)d_in[2],
        (const float*)d_in[3], (const float*)d_in[4],
        (const float*)d_in[5], (const float*)d_in[6],
        (const float*)d_in[7], (const float*)d_in[8],
        (const float*)d_in[9], (const float*)d_in[10],
        (float*)d_out);
}

// round 2
// speedup vs baseline: 1.1173x; 1.1173x over previous
#include <cuda_runtime.h>
#include <cuda_fp16.h>

#define T_STEPS 8192
#define HDIM    1024
#define IN_DIM  9
#define GDIM    (4 * HDIM)      // 4096 gate rows
#define NC0     54
#define NC1     94
#define NCTA    (NC0 + NC1)
#define NTHR    256

// Persistent device scratch (static __device__ arrays: allowed, zero-init .bss).
__device__ __align__(16) float g_gx0[(size_t)T_STEPS * GDIM];  // precomputed W_ih0.x + biases
__device__ __align__(16) float g_h0[(size_t)T_STEPS * HDIM];
__device__ __align__(16) float g_h1[(size_t)T_STEPS * HDIM];
__device__ unsigned long long g_ctr[32];                       // [0]=c0, [16]=c1 (128B apart)

// SMEM layout (bytes). Weight region worst case:
//   L0: 76 rows x 1024 halfs = 155648 B;  L1: 2 x (44 x 1024 halfs) = 180224 B.
#define OFF_SWB  90112           // L1 phase-B weights (Whh1 slice)
#define OFF_SV   180224          // float[1024] staged v
#define OFF_SB   184320          // float[96]  biases (L1)
#define OFF_SG   184832          // float[96]  gate preactivations
#define OFF_SC   185344          // float[32]  cell state
#define SMEM_BYTES 185472

__device__ __forceinline__ float fsig(float x) {
    return __fdividef(1.0f, 1.0f + __expf(-x));
}
__device__ __forceinline__ float ftanh_(float x) {
    float a = fabsf(x);
    float e = __expf(-2.0f * a);
    return copysignf(__fdividef(1.0f - e, 1.0f + e), x);
}

__device__ __forceinline__ unsigned long long atom_add_release(unsigned long long* p) {
    unsigned long long old;
    asm volatile("atom.release.gpu.global.add.u64 %0, [%1], 1;"
                 : "=l"(old) : "l"(p) : "memory");
    return old;
}
__device__ __forceinline__ unsigned long long ld_acquire(const unsigned long long* p) {
    unsigned long long v;
    asm volatile("ld.acquire.gpu.global.u64 %0, [%1];" : "=l"(v) : "l"(p) : "memory");
    return v;
}
__device__ __forceinline__ void wait_ge(const unsigned long long* p, unsigned long long tgt) {
    while (ld_acquire(p) < tgt) { }
}

// Warp-per-row-pair dot products over K=1024: fp16 weights in SMEM (LDS.128,
// conflict-free), fp32 v cached in registers, fp32 accumulation.
// MODE 0: sg[r] = acc            (L0; bias+x folded into gx0)
// MODE 1: sg[r] = acc + sb[r]    (L1 phase A)
// MODE 2: sg[r] += acc           (L1 phase B)
template<int MODE>
__device__ __forceinline__ void compute_rows(const __half* __restrict__ sw,
                                             const float*  __restrict__ sv,
                                             const float*  __restrict__ sb,
                                             float*        __restrict__ sg,
                                             int nrows)
{
    const int wid  = threadIdx.x >> 5;
    const int lane = threadIdx.x & 31;

    float vr[32];
#pragma unroll
    for (int it = 0; it < 4; ++it) {
        const float4* p = (const float4*)(sv + (it * 32 + lane) * 8);
        float4 a = p[0], b = p[1];
        vr[it*8+0]=a.x; vr[it*8+1]=a.y; vr[it*8+2]=a.z; vr[it*8+3]=a.w;
        vr[it*8+4]=b.x; vr[it*8+5]=b.y; vr[it*8+6]=b.z; vr[it*8+7]=b.w;
    }

    for (int r0 = wid; r0 < nrows; r0 += 16) {
        const int  r1   = r0 + 8;
        const bool has1 = (r1 < nrows);
        float acc0 = 0.f, acc1 = 0.f;
        const uint4* w0 = (const uint4*)(sw + (size_t)r0 * 1024);
        const uint4* w1 = (const uint4*)(sw + (size_t)(has1 ? r1 : r0) * 1024);
#pragma unroll
        for (int it = 0; it < 4; ++it) {
            uint4 aw = w0[it * 32 + lane];
            uint4 bw = w1[it * 32 + lane];
            const __half2* ah = (const __half2*)&aw;
            const __half2* bh = (const __half2*)&bw;
#pragma unroll
            for (int q = 0; q < 4; ++q) {
                float2 fa = __half22float2(ah[q]);
                float2 fb = __half22float2(bh[q]);
                acc0 = fmaf(fa.x, vr[it*8+q*2+0], acc0);
                acc1 = fmaf(fb.x, vr[it*8+q*2+0], acc1);
                acc0 = fmaf(fa.y, vr[it*8+q*2+1], acc0);
                acc1 = fmaf(fb.y, vr[it*8+q*2+1], acc1);
            }
        }
#pragma unroll
        for (int off = 16; off; off >>= 1) {
            acc0 += __shfl_xor_sync(0xffffffffu, acc0, off);
            acc1 += __shfl_xor_sync(0xffffffffu, acc1, off);
        }
        if (lane == 0) {
            if (MODE == 0)      sg[r0] = acc0;
            else if (MODE == 1) sg[r0] = acc0 + sb[r0];
            else                sg[r0] += acc0;
            if (has1) {
                if (MODE == 0)      sg[r1] = acc1;
                else if (MODE == 1) sg[r1] = acc1 + sb[r1];
                else                sg[r1] += acc1;
            }
        }
    }
}

// ---- Pre-kernel: gx0[t][(j,gate)] = W_ih0[R].x[t] + b_ih0[R] + b_hh0[R],
//      R = gate*H + j, stored at t*GDIM + j*4 + gate (contiguous per-CTA). ----
__global__ void gx0_kernel(const float* __restrict__ x,
                           const float* __restrict__ wih0,
                           const float* __restrict__ bih0,
                           const float* __restrict__ bhh0)
{
    int idx = blockIdx.x * blockDim.x + threadIdx.x;
    if (idx >= T_STEPS * GDIM) return;
    int t = idx >> 12, rp = idx & 4095;
    int j = rp >> 2, gate = rp & 3;
    int R = (gate << 10) + j;
    const float* w  = wih0 + R * IN_DIM;
    const float* xv = x + t * IN_DIM;
    float a = bih0[R] + bhh0[R];
#pragma unroll
    for (int q = 0; q < IN_DIM; ++q) a = fmaf(w[q], xv[q], a);
    g_gx0[idx] = a;
}

__global__ void init_kernel() {
    if (threadIdx.x < 32) g_ctr[threadIdx.x] = 0ULL;
}

__global__ void __launch_bounds__(NTHR, 1)
lstm_kernel(const float* __restrict__ whh0,
            const float* __restrict__ wih1, const float* __restrict__ whh1,
            const float* __restrict__ bih1, const float* __restrict__ bhh1,
            const float* __restrict__ wlin, const float* __restrict__ blin,
            float* __restrict__ out)
{
    extern __shared__ char smem[];
    __half* sw  = (__half*)smem;                    // L0: Whh0 | L1: Wih1 slice
    __half* swB = (__half*)(smem + OFF_SWB);        // L1: Whh1 slice
    float*  sv  = (float*)(smem + OFF_SV);
    float*  sb  = (float*)(smem + OFF_SB);
    float*  sg  = (float*)(smem + OFF_SG);
    float*  sc  = (float*)(smem + OFF_SC);

    unsigned long long* c0 = &g_ctr[0];
    unsigned long long* c1 = &g_ctr[16];

    const int  bid  = blockIdx.x;
    const int  tid  = threadIdx.x;
    const bool isL0 = (bid < NC0);
    const int  lb   = isL0 ? bid : (bid - NC0);
    const int  np   = isL0 ? NC0 : NC1;
    const int  j0   = lb * HDIM / np;
    const int  j1   = (lb + 1) * HDIM / np;
    const int  nj   = j1 - j0;
    const int  nrows = nj * 4;

    // ---- Prologue: stage weight slices as fp16 (local row lr = jl*4+gate,
    //      global row R = gate*H + j0 + jl; PyTorch gate order i,f,g,o) ----
    if (isL0) {
        const int tot = nrows << 10;
        for (int idx = tid; idx < tot; idx += NTHR) {
            int lr = idx >> 10, k = idx & 1023;
            int R = ((lr & 3) << 10) + j0 + (lr >> 2);
            sw[idx] = __float2half(whh0[((size_t)R << 10) + k]);
        }
    } else {
        const int tot = nrows << 10;
        for (int idx = tid; idx < tot; idx += NTHR) {
            int lr = idx >> 10, k = idx & 1023;
            int R = ((lr & 3) << 10) + j0 + (lr >> 2);
            sw[idx]  = __float2half(wih1[((size_t)R << 10) + k]);
            swB[idx] = __float2half(whh1[((size_t)R << 10) + k]);
        }
        for (int lr = tid; lr < nrows; lr += NTHR) {
            int R = ((lr & 3) << 10) + j0 + (lr >> 2);
            sb[lr] = bih1[R] + bhh1[R];
        }
    }
    __syncthreads();

    if (isL0) {
        // ======== Layer 0 chain: waits only on L0 peers ========
        for (int t = 0; t < T_STEPS; ++t) {
            if (t > 0) {
                if (tid == 0) wait_ge(c0, (unsigned long long)NC0 * t);
                __syncthreads();
            }
            float4* d = (float4*)sv;
            d[tid] = (t == 0) ? make_float4(0.f,0.f,0.f,0.f)
                              : ((const float4*)(g_h0 + (size_t)(t - 1) * HDIM))[tid];
            __syncthreads();

            // Prefetch gx0 early so its DRAM latency hides under the matvec.
            float4 gx = make_float4(0.f,0.f,0.f,0.f);
            if (tid < nj)
                gx = *(const float4*)(g_gx0 + (size_t)t * GDIM + (size_t)(j0 + tid) * 4);

            compute_rows<0>(sw, sv, nullptr, sg, nrows);
            __syncthreads();

            if (tid < nj) {
                float gi = sg[tid*4+0] + gx.x, gf = sg[tid*4+1] + gx.y;
                float gc = sg[tid*4+2] + gx.z, go = sg[tid*4+3] + gx.w;
                float i_ = fsig(gi), f_ = fsig(gf), ci = ftanh_(gc), o_ = fsig(go);
                float cp = (t == 0) ? 0.f : sc[tid];
                float c  = fmaf(f_, cp, i_ * ci);
                sc[tid] = c;
                g_h0[(size_t)t * HDIM + j0 + tid] = o_ * ftanh_(c);
            }
            __syncthreads();
            if (tid == 0) atom_add_release(c0);   // release orders the h stores
        }
    } else {
        // ======== Layer 1 chain: phase A (vs h0[t], early) + phase B (vs h1[t-1]) ========
        for (int t = 0; t < T_STEPS; ++t) {
            // Phase A: W_ih1 . h0[t]  — L0 runs ahead, wait is ~free; this
            // compute also hides the peers' release propagation for phase B.
            if (tid == 0) wait_ge(c0, (unsigned long long)NC0 * (t + 1));
            __syncthreads();
            ((float4*)sv)[tid] = ((const float4*)(g_h0 + (size_t)t * HDIM))[tid];
            __syncthreads();
            compute_rows<1>(sw, sv, sb, sg, nrows);
            __syncthreads();

            // Phase B: W_hh1 . h1[t-1]
            if (t > 0) {
                if (tid == 0) wait_ge(c1, (unsigned long long)NC1 * t);
                __syncthreads();
            }
            ((float4*)sv)[tid] = (t == 0) ? make_float4(0.f,0.f,0.f,0.f)
                                          : ((const float4*)(g_h1 + (size_t)(t - 1) * HDIM))[tid];
            __syncthreads();
            compute_rows<2>(swB, sv, nullptr, sg, nrows);
            __syncthreads();

            if (tid < nj) {
                float gi = sg[tid*4+0], gf = sg[tid*4+1];
                float gc = sg[tid*4+2], go = sg[tid*4+3];
                float i_ = fsig(gi), f_ = fsig(gf), ci = ftanh_(gc), o_ = fsig(go);
                float cp = (t == 0) ? 0.f : sc[tid];
                float c  = fmaf(f_, cp, i_ * ci);
                sc[tid] = c;
                g_h1[(size_t)t * HDIM + j0 + tid] = o_ * ftanh_(c);
            }
            __syncthreads();
            if (tid == 0) atom_add_release(c1);
        }

        // ---- Final linear (designated CTA) ----
        if (bid == NC0) {
            if (tid == 0) wait_ge(c1, (unsigned long long)NC1 * T_STEPS);
            __syncthreads();
            const float* hl = g_h1 + (size_t)(T_STEPS - 1) * HDIM;
            float p = 0.f;
            for (int k = tid; k < HDIM; k += NTHR) p = fmaf(hl[k], wlin[k], p);
#pragma unroll
            for (int off = 16; off; off >>= 1) p += __shfl_xor_sync(0xffffffffu, p, off);
            if ((tid & 31) == 0) sv[tid >> 5] = p;
            __syncthreads();
            if (tid == 0) {
                float sres = blin[0];
                for (int w = 0; w < 8; ++w) sres += sv[w];
                out[0] = sres;
            }
        }
    }
}

extern "C" void kernel_launch(void* const* d_in, const int* in_sizes, int n_in,
                              void* d_out, int out_size)
{
    cudaFuncSetAttribute(lstm_kernel,
                         cudaFuncAttributeMaxDynamicSharedMemorySize, SMEM_BYTES);

    init_kernel<<<1, 32>>>();
    gx0_kernel<<<(T_STEPS * GDIM + 255) / 256, 256>>>(
        (const float*)d_in[0], (const float*)d_in[1],
        (const float*)d_in[3], (const float*)d_in[4]);
    lstm_kernel<<<NCTA, NTHR, SMEM_BYTES>>>(
        (const float*)d_in[2],                       // whh0
        (const float*)d_in[5], (const float*)d_in[6],// wih1, whh1
        (const float*)d_in[7], (const float*)d_in[8],// bih1, bhh1
        (const float*)d_in[9], (const float*)d_in[10],
        (float*)d_out);
}

// round 7
// speedup vs baseline: 1.4300x; 1.2798x over previous
#include <cuda_runtime.h>
#include <cuda_fp16.h>
#include <cstdint>

#define T_STEPS 8192
#define HDIM    1024
#define IN_DIM  9
#define GDIM    (4 * HDIM)
#define NC0     52          // layer-0 CTAs: nj<=20, 80 rows = 5 m-tiles
#define NC1     86          // layer-1 CTAs: nj<=12, 48 rows = 3 m-tiles
#define NCTA    (NC0 + NC1)
#define NTHR    512         // 16 warps: warp w owns K range [64w, 64w+64)

typedef unsigned int u32;
typedef unsigned long long u64;

// Persistent device scratch. h kept in fp32; fp16 hi/lo split happens at
// B-fragment load so the MMA sees (v_hi + v_lo) ~= fp32 v.
__device__ __align__(16) float g_gx0[(size_t)T_STEPS * GDIM]; // W_ih0.x + b, layout [t][j*4+gate]
__device__ __align__(16) float g_h0[(size_t)T_STEPS * HDIM];
__device__ __align__(16) float g_h1[(size_t)T_STEPS * HDIM];
__device__ u64 g_ctr[32];                                     // [0]=c0, [16]=c1

__device__ __forceinline__ float fsig(float x) {
    return __fdividef(1.0f, 1.0f + __expf(-x));
}
__device__ __forceinline__ float ftanh_(float x) {
    float a = fabsf(x);
    float e = __expf(-2.0f * a);
    return copysignf(__fdividef(1.0f - e, 1.0f + e), x);
}
__device__ __forceinline__ u64 ld_acquire(const u64* p) {
    u64 v;
    asm volatile("ld.acquire.gpu.global.u64 %0, [%1];" : "=l"(v) : "l"(p) : "memory");
    return v;
}
__device__ __forceinline__ void wait_ge(const u64* p, u64 tgt) {
    while (ld_acquire(p) < tgt) { }
}
__device__ __forceinline__ void red_release(u64* p) {
    asm volatile("red.release.gpu.global.add.u64 [%0], 1;" :: "l"(p) : "memory");
}

__device__ __forceinline__ void mma_one(float* acc, const u32* a, u32 b0, u32 b1) {
    asm volatile(
        "mma.sync.aligned.m16n8k16.row.col.f32.f16.f16.f32 "
        "{%0,%1,%2,%3},{%4,%5,%6,%7},{%8,%9},{%0,%1,%2,%3};"
        : "+f"(acc[0]), "+f"(acc[1]), "+f"(acc[2]), "+f"(acc[3])
        : "r"(a[0]), "r"(a[1]), "r"(a[2]), "r"(a[3]), "r"(b0), "r"(b1));
}

// ---- Load persistent A fragments (m16n8k16 row-major A) from fp32 weights.
// Warp w (of 16) owns K range [64w, 64w+64) = 4 k16 chunks. Local row
// lr = jl*4+gate, global weight row R = gate*HDIM + j0 + jl (gate order i,f,g,o).
// A-frag map: a0=A[gid][2tg..+1], a1=A[gid+8][..], a2=A[gid][2tg+8..+9], a3=A[gid+8][..].
template<int NT>
__device__ __forceinline__ void load_frags(u32 af[][4][4],
                                           const float* __restrict__ W,
                                           int j0, int nrows,
                                           int wid, int gid, int tg)
{
#pragma unroll
    for (int mt = 0; mt < NT; ++mt) {
#pragma unroll
        for (int kc = 0; kc < 4; ++kc) {
            const int k0 = wid * 64 + kc * 16;
#pragma unroll
            for (int i = 0; i < 4; ++i) {
                const int lr = mt * 16 + ((i & 1) ? 8 : 0) + gid;
                const int c  = k0 + 2 * tg + ((i & 2) ? 8 : 0);
                u32 v = 0u;
                if (lr < nrows) {
                    const int jl = lr >> 2, gate = lr & 3;
                    const float2 w2 = *(const float2*)(W +
                        ((size_t)((gate << 10) + j0 + jl) << 10) + c);
                    const __half2 h2 = __floats2half2_rn(w2.x, w2.y);
                    v = *(const u32*)&h2;
                }
                af[mt][kc][i] = v;
            }
        }
    }
}

// ---- One matvec phase with hi/lo split: acc += A * hi(v) + A * lo(v).
// B col 0 = v, cols 1-7 = 0. B-frag map: b0 = v[k0+2tg..+1] (col gid==0 only),
// b1 = v[k0+2tg+8..+9].
template<int NT>
__device__ __forceinline__ void mma_phase(float acc[][4],
                                          const u32 af[][4][4],
                                          const float* __restrict__ v,
                                          int wid, int gid, int tg)
{
#pragma unroll
    for (int kc = 0; kc < 4; ++kc) {
        u32 bh0 = 0u, bh1 = 0u, bl0 = 0u, bl1 = 0u;
        if (gid == 0) {
            const int k0 = wid * 64 + kc * 16 + 2 * tg;
            const float2 p = *(const float2*)(v + k0);
            const float2 q = *(const float2*)(v + k0 + 8);
            const __half2 ph = __floats2half2_rn(p.x, p.y);
            const __half2 qh = __floats2half2_rn(q.x, q.y);
            const float2 pf = __half22float2(ph);
            const float2 qf = __half22float2(qh);
            const __half2 pl = __floats2half2_rn(p.x - pf.x, p.y - pf.y);
            const __half2 ql = __floats2half2_rn(q.x - qf.x, q.y - qf.y);
            bh0 = *(const u32*)&ph; bh1 = *(const u32*)&qh;
            bl0 = *(const u32*)&pl; bl1 = *(const u32*)&ql;
        }
#pragma unroll
        for (int mt = 0; mt < NT; ++mt) {
            mma_one(acc[mt], af[mt][kc], bh0, bh1);
        }
#pragma unroll
        for (int mt = 0; mt < NT; ++mt) {
            mma_one(acc[mt], af[mt][kc], bl0, bl1);
        }
    }
}

// Column-0 results live in lanes with tg==0: acc[mt][0] = row 16mt+gid,
// acc[mt][2] = row 16mt+8+gid. sp stride 17 floats dodges bank conflicts.
template<int NT>
__device__ __forceinline__ void store_partials(const float acc[][4],
                                               float* __restrict__ sp,
                                               int wid, int gid, int tg)
{
    if (tg == 0) {
#pragma unroll
        for (int mt = 0; mt < NT; ++mt) {
            sp[(mt * 16 + gid) * 17 + wid]     = acc[mt][0];
            sp[(mt * 16 + 8 + gid) * 17 + wid] = acc[mt][2];
        }
    }
}

// ---- Pre-kernel: gx0[t][j*4+gate] = W_ih0[R].x[t] + b_ih0[R] + b_hh0[R]. ----
__global__ void gx0_kernel(const float* __restrict__ x,
                           const float* __restrict__ wih0,
                           const float* __restrict__ bih0,
                           const float* __restrict__ bhh0)
{
    int idx = blockIdx.x * blockDim.x + threadIdx.x;
    if (idx >= T_STEPS * GDIM) return;
    int t = idx >> 12, rp = idx & 4095;
    int j = rp >> 2, gate = rp & 3;
    int R = (gate << 10) + j;
    const float* w  = wih0 + R * IN_DIM;
    const float* xv = x + t * IN_DIM;
    float a = bih0[R] + bhh0[R];
#pragma unroll
    for (int q = 0; q < IN_DIM; ++q) {
        a = fmaf(w[q], xv[q], a);
    }
    g_gx0[idx] = a;
}

__global__ void init_kernel() {
    if (threadIdx.x < 32) g_ctr[threadIdx.x] = 0ULL;
}

__global__ void __launch_bounds__(NTHR, 1)
lstm_kernel(const float* __restrict__ whh0,
            const float* __restrict__ wih1, const float* __restrict__ whh1,
            const float* __restrict__ bih1, const float* __restrict__ bhh1,
            const float* __restrict__ wlin, const float* __restrict__ blin,
            float* __restrict__ out)
{
    __shared__ float sp[80 * 17];
    __shared__ float sb[80];
    __shared__ float sg[80];
    __shared__ float sc[32];
    __shared__ float sred[16];

    u64* c0 = &g_ctr[0];
    u64* c1 = &g_ctr[16];

    const int tid  = threadIdx.x;
    const int wid  = tid >> 5;          // 0..15
    const int lane = tid & 31;
    const int gid  = lane >> 2;
    const int tg   = lane & 3;
    const int bid  = blockIdx.x;
    const bool isL0 = (bid < NC0);
    const int lb = isL0 ? bid : (bid - NC0);
    const int np = isL0 ? NC0 : NC1;
    const int j0 = lb * HDIM / np;
    const int j1 = (lb + 1) * HDIM / np;
    const int nj = j1 - j0;
    const int nrows = nj * 4;

    if (isL0) {
        // ================= Layer 0 chain =================
        u32 af0[5][4][4];
        load_frags<5>(af0, whh0, j0, nrows, wid, gid, tg);
        __syncthreads();

        for (int t = 0; t < T_STEPS; ++t) {
            // Prefetch this step's input-gate contribution (DRAM) early.
            float4 gx = make_float4(0.f, 0.f, 0.f, 0.f);
            if (tid < nj) {
                gx = __ldg((const float4*)(g_gx0 + ((size_t)t << 12) +
                                           (size_t)(j0 + tid) * 4));
            }
            if (t > 0) {
                if (tid == 0) wait_ge(c0, 32ULL * NC0 * (u64)t);
                __syncthreads();
            }
            float acc[5][4];
#pragma unroll
            for (int mt = 0; mt < 5; ++mt) {
#pragma unroll
                for (int i = 0; i < 4; ++i) acc[mt][i] = 0.f;
            }
            if (t > 0) {
                mma_phase<5>(acc, af0, g_h0 + (size_t)(t - 1) * HDIM, wid, gid, tg);
            }
            store_partials<5>(acc, sp, wid, gid, tg);
            __syncthreads();
            if (tid < 80) {
                float s = 0.f;
#pragma unroll
                for (int w = 0; w < 16; ++w) s += sp[tid * 17 + w];
                sg[tid] = s;
            }
            __syncthreads();
            if (wid == 0) {
                if (tid < nj) {
                    float gi = sg[tid*4+0] + gx.x, gf = sg[tid*4+1] + gx.y;
                    float gc = sg[tid*4+2] + gx.z, go = sg[tid*4+3] + gx.w;
                    float i_ = fsig(gi), f_ = fsig(gf);
                    float ci = ftanh_(gc), o_ = fsig(go);
                    float cp = (t == 0) ? 0.f : sc[tid];
                    float c  = fmaf(f_, cp, i_ * ci);
                    sc[tid] = c;
                    g_h0[(size_t)t * HDIM + j0 + tid] = o_ * ftanh_(c);
                }
                __syncwarp();
                red_release(c0);   // 32 incr/CTA/step; each lane orders its own store
            }
        }
    } else {
        // ================= Layer 1 chain =================
        u32 afA[3][4][4], afB[3][4][4];
        load_frags<3>(afA, wih1, j0, nrows, wid, gid, tg);
        load_frags<3>(afB, whh1, j0, nrows, wid, gid, tg);
        for (int r = tid; r < 80; r += NTHR) sb[r] = 0.f;
        __syncthreads();
        for (int lr = tid; lr < nrows; lr += NTHR) {
            int R = ((lr & 3) << 10) + j0 + (lr >> 2);
            sb[lr] = bih1[R] + bhh1[R];
        }
        __syncthreads();

        for (int t = 0; t < T_STEPS; ++t) {
            // Phase A: W_ih1 . h0[t]  (L0 runs ahead; off the h1 critical path)
            if (tid == 0) wait_ge(c0, 32ULL * NC0 * (u64)(t + 1));
            __syncthreads();
            float acc[3][4];
#pragma unroll
            for (int mt = 0; mt < 3; ++mt) {
#pragma unroll
                for (int i = 0; i < 4; ++i) acc[mt][i] = 0.f;
            }
            mma_phase<3>(acc, afA, g_h0 + (size_t)t * HDIM, wid, gid, tg);

            // Phase B: W_hh1 . h1[t-1]
            if (t > 0) {
                if (tid == 0) wait_ge(c1, 32ULL * NC1 * (u64)t);
                __syncthreads();
                mma_phase<3>(acc, afB, g_h1 + (size_t)(t - 1) * HDIM, wid, gid, tg);
            }
            store_partials<3>(acc, sp, wid, gid, tg);
            __syncthreads();
            if (tid < 48) {
                float s = sb[tid];
#pragma unroll
                for (int w = 0; w < 16; ++w) s += sp[tid * 17 + w];
                sg[tid] = s;
            }
            __syncthreads();
            if (wid == 0) {
                if (tid < nj) {
                    float gi = sg[tid*4+0], gf = sg[tid*4+1];
                    float gc = sg[tid*4+2], go = sg[tid*4+3];
                    float i_ = fsig(gi), f_ = fsig(gf);
                    float ci = ftanh_(gc), o_ = fsig(go);
                    float cp = (t == 0) ? 0.f : sc[tid];
                    float c  = fmaf(f_, cp, i_ * ci);
                    sc[tid] = c;
                    g_h1[(size_t)t * HDIM + j0 + tid] = o_ * ftanh_(c);
                }
                __syncwarp();
                red_release(c1);
            }
        }

        // ---- Final linear (first L1 CTA) ----
        if (bid == NC0) {
            if (tid == 0) wait_ge(c1, 32ULL * NC1 * (u64)T_STEPS);
            __syncthreads();
            const float* hl = g_h1 + (size_t)(T_STEPS - 1) * HDIM;
            float p = 0.f;
            for (int k = tid; k < HDIM; k += NTHR) {
                p = fmaf(hl[k], wlin[k], p);
            }
#pragma unroll
            for (int off = 16; off; off >>= 1) {
                p += __shfl_xor_sync(0xffffffffu, p, off);
            }
            if (lane == 0) sred[wid] = p;
            __syncthreads();
            if (tid == 0) {
                float sres = blin[0];
#pragma unroll
                for (int w = 0; w < 16; ++w) sres += sred[w];
                out[0] = sres;
            }
        }
    }
}

extern "C" void kernel_launch(void* const* d_in, const int* in_sizes, int n_in,
                              void* d_out, int out_size)
{
    init_kernel<<<1, 32>>>();
    gx0_kernel<<<(T_STEPS * GDIM + 255) / 256, 256>>>(
        (const float*)d_in[0], (const float*)d_in[1],
        (const float*)d_in[3], (const float*)d_in[4]);
    lstm_kernel<<<NCTA, NTHR>>>(
        (const float*)d_in[2],                        // w_hh0
        (const float*)d_in[5], (const float*)d_in[6], // w_ih1, w_hh1
        (const float*)d_in[7], (const float*)d_in[8], // b_ih1, b_hh1
        (const float*)d_in[9], (const float*)d_in[10],
        (float*)d_out);
}

// round 8
// speedup vs baseline: 1.6468x; 1.1516x over previous
#include <cuda_runtime.h>
#include <cuda_fp16.h>
#include <cstdint>

#define T_STEPS 8192
#define HDIM    1024
#define IN_DIM  9
#define GDIM    (4 * HDIM)
#define NC0     52          // layer-0 CTAs: nj<=20, 80 rows = 5 m-tiles
#define NC1     86          // layer-1 CTAs: nj<=12, 48 rows = 3 m-tiles
#define NCTA    (NC0 + NC1)
#define NTHR    512         // 16 warps: warp w owns K range [64w, 64w+64)

typedef unsigned int u32;
typedef unsigned long long u64;

// Persistent device scratch. h stored as pre-split fp16 hi/lo pairs so the
// MMA consumes (hi + lo) ~= fp32 h with no conversion on the consumer path.
__device__ __align__(16) float  g_gx0[(size_t)T_STEPS * GDIM]; // W_ih0.x + b, [t][j*4+gate]
__device__ __align__(16) __half g_h0h[(size_t)T_STEPS * HDIM];
__device__ __align__(16) __half g_h0l[(size_t)T_STEPS * HDIM];
__device__ __align__(16) __half g_h1h[(size_t)T_STEPS * HDIM];
__device__ __align__(16) __half g_h1l[(size_t)T_STEPS * HDIM];
__device__ u64 g_ctr[32];                                      // [0]=c0, [16]=c1

__device__ __forceinline__ float fsig(float x) {
    return __fdividef(1.0f, 1.0f + __expf(-x));
}
__device__ __forceinline__ float ftanh_(float x) {
    float a = fabsf(x);
    float e = __expf(-2.0f * a);
    return copysignf(__fdividef(1.0f - e, 1.0f + e), x);
}
__device__ __forceinline__ u64 ld_acquire(const u64* p) {
    u64 v;
    asm volatile("ld.acquire.gpu.global.u64 %0, [%1];" : "=l"(v) : "l"(p) : "memory");
    return v;
}
__device__ __forceinline__ void wait_ge(const u64* p, u64 tgt) {
    while (ld_acquire(p) < tgt) { }
}
__device__ __forceinline__ void red_release(u64* p) {
    asm volatile("red.release.gpu.global.add.u64 [%0], 1;" :: "l"(p) : "memory");
}

__device__ __forceinline__ void mma_one(float* acc, const u32* a, u32 b0, u32 b1) {
    asm volatile(
        "mma.sync.aligned.m16n8k16.row.col.f32.f16.f16.f32 "
        "{%0,%1,%2,%3},{%4,%5,%6,%7},{%8,%9},{%0,%1,%2,%3};"
        : "+f"(acc[0]), "+f"(acc[1]), "+f"(acc[2]), "+f"(acc[3])
        : "r"(a[0]), "r"(a[1]), "r"(a[2]), "r"(a[3]), "r"(b0), "r"(b1));
}

// ---- Load persistent A fragments (m16n8k16 row-major A) from fp32 weights.
// Warp w (of 16) owns K range [64w, 64w+64) = 4 k16 chunks. Local row
// lr = jl*4+gate, global weight row R = gate*HDIM + j0 + jl (gate order i,f,g,o).
// A-frag map: a0=A[gid][2tg..+1], a1=A[gid+8][..], a2=A[gid][2tg+8..+9], a3=A[gid+8][..].
template<int NT>
__device__ __forceinline__ void load_frags(u32 af[][4][4],
                                           const float* __restrict__ W,
                                           int j0, int nrows,
                                           int wid, int gid, int tg)
{
#pragma unroll
    for (int mt = 0; mt < NT; ++mt) {
#pragma unroll
        for (int kc = 0; kc < 4; ++kc) {
            const int k0 = wid * 64 + kc * 16;
#pragma unroll
            for (int i = 0; i < 4; ++i) {
                const int lr = mt * 16 + ((i & 1) ? 8 : 0) + gid;
                const int c  = k0 + 2 * tg + ((i & 2) ? 8 : 0);
                u32 v = 0u;
                if (lr < nrows) {
                    const int jl = lr >> 2, gate = lr & 3;
                    const float2 w2 = *(const float2*)(W +
                        ((size_t)((gate << 10) + j0 + jl) << 10) + c);
                    const __half2 h2 = __floats2half2_rn(w2.x, w2.y);
                    v = *(const u32*)&h2;
                }
                af[mt][kc][i] = v;
            }
        }
    }
}

// ---- One matvec phase: acc += A * vh + A * vl (pre-split hi/lo fp16 vectors).
// B col 0 = v, cols 1-7 = 0. B-frag map: b0 = v[k0+2tg..+1] (col gid==0 only),
// b1 = v[k0+2tg+8..+9].
template<int NT>
__device__ __forceinline__ void mma_phase(float acc[][4],
                                          const u32 af[][4][4],
                                          const __half* __restrict__ vh,
                                          const __half* __restrict__ vl,
                                          int wid, int gid, int tg)
{
#pragma unroll
    for (int kc = 0; kc < 4; ++kc) {
        u32 bh0 = 0u, bh1 = 0u, bl0 = 0u, bl1 = 0u;
        if (gid == 0) {
            const int k0 = wid * 64 + kc * 16 + 2 * tg;
            bh0 = *(const u32*)(vh + k0);
            bh1 = *(const u32*)(vh + k0 + 8);
            bl0 = *(const u32*)(vl + k0);
            bl1 = *(const u32*)(vl + k0 + 8);
        }
#pragma unroll
        for (int mt = 0; mt < NT; ++mt) {
            mma_one(acc[mt], af[mt][kc], bh0, bh1);
        }
#pragma unroll
        for (int mt = 0; mt < NT; ++mt) {
            mma_one(acc[mt], af[mt][kc], bl0, bl1);
        }
    }
}

// Column-0 results live in lanes with tg==0: acc[mt][0] = row 16mt+gid,
// acc[mt][2] = row 16mt+8+gid. sp stride 17 floats dodges bank conflicts.
template<int NT>
__device__ __forceinline__ void store_partials(const float acc[][4],
                                               float* __restrict__ sp,
                                               int wid, int gid, int tg)
{
    if (tg == 0) {
#pragma unroll
        for (int mt = 0; mt < NT; ++mt) {
            sp[(mt * 16 + gid) * 17 + wid]     = acc[mt][0];
            sp[(mt * 16 + 8 + gid) * 17 + wid] = acc[mt][2];
        }
    }
}

// ---- Pre-kernel: gx0[t][j*4+gate] = W_ih0[R].x[t] + b_ih0[R] + b_hh0[R]. ----
__global__ void gx0_kernel(const float* __restrict__ x,
                           const float* __restrict__ wih0,
                           const float* __restrict__ bih0,
                           const float* __restrict__ bhh0)
{
    int idx = blockIdx.x * blockDim.x + threadIdx.x;
    if (idx >= T_STEPS * GDIM) return;
    int t = idx >> 12, rp = idx & 4095;
    int j = rp >> 2, gate = rp & 3;
    int R = (gate << 10) + j;
    const float* w  = wih0 + R * IN_DIM;
    const float* xv = x + t * IN_DIM;
    float a = bih0[R] + bhh0[R];
#pragma unroll
    for (int q = 0; q < IN_DIM; ++q) {
        a = fmaf(w[q], xv[q], a);
    }
    g_gx0[idx] = a;
}

__global__ void init_kernel() {
    if (threadIdx.x < 32) g_ctr[threadIdx.x] = 0ULL;
}

__global__ void __launch_bounds__(NTHR, 1)
lstm_kernel(const float* __restrict__ whh0,
            const float* __restrict__ wih1, const float* __restrict__ whh1,
            const float* __restrict__ bih1, const float* __restrict__ bhh1,
            const float* __restrict__ wlin, const float* __restrict__ blin,
            float* __restrict__ out)
{
    __shared__ float sp[80 * 17];
    __shared__ float sb[80];
    __shared__ float sg[80];
    __shared__ float sc[32];
    __shared__ float sred[16];

    u64* c0 = &g_ctr[0];
    u64* c1 = &g_ctr[16];

    const int tid  = threadIdx.x;
    const int wid  = tid >> 5;          // 0..15
    const int lane = tid & 31;
    const int gid  = lane >> 2;
    const int tg   = lane & 3;
    const int bid  = blockIdx.x;
    const bool isL0 = (bid < NC0);
    const int lb = isL0 ? bid : (bid - NC0);
    const int np = isL0 ? NC0 : NC1;
    const int j0 = lb * HDIM / np;
    const int j1 = (lb + 1) * HDIM / np;
    const int nj = j1 - j0;
    const int nrows = nj * 4;

    if (isL0) {
        // ================= Layer 0 chain =================
        u32 af0[5][4][4];
        load_frags<5>(af0, whh0, j0, nrows, wid, gid, tg);
        __syncthreads();

        for (int t = 0; t < T_STEPS; ++t) {
            // Prefetch this step's input-gate contribution (DRAM) early.
            float4 gx = make_float4(0.f, 0.f, 0.f, 0.f);
            if (tid < nj) {
                gx = __ldg((const float4*)(g_gx0 + ((size_t)t << 12) +
                                           (size_t)(j0 + tid) * 4));
            }
            if (t > 0) {
                if (tid == 0) wait_ge(c0, (u64)NC0 * (u64)t);
                __syncthreads();
            }
            float acc[5][4];
#pragma unroll
            for (int mt = 0; mt < 5; ++mt) {
#pragma unroll
                for (int i = 0; i < 4; ++i) acc[mt][i] = 0.f;
            }
            if (t > 0) {
                mma_phase<5>(acc, af0,
                             g_h0h + (size_t)(t - 1) * HDIM,
                             g_h0l + (size_t)(t - 1) * HDIM, wid, gid, tg);
            }
            store_partials<5>(acc, sp, wid, gid, tg);
            __syncthreads();
            if (tid < 80) {
                float s = 0.f;
#pragma unroll
                for (int w = 0; w < 16; ++w) s += sp[tid * 17 + w];
                sg[tid] = s;
            }
            __syncthreads();
            if (wid == 0) {
                if (tid < nj) {
                    float gi = sg[tid*4+0] + gx.x, gf = sg[tid*4+1] + gx.y;
                    float gc = sg[tid*4+2] + gx.z, go = sg[tid*4+3] + gx.w;
                    float i_ = fsig(gi), f_ = fsig(gf);
                    float ci = ftanh_(gc), o_ = fsig(go);
                    float cp = (t == 0) ? 0.f : sc[tid];
                    float c  = fmaf(f_, cp, i_ * ci);
                    sc[tid] = c;
                    float h = o_ * ftanh_(c);
                    __half hh = __float2half(h);
                    __half hl = __float2half(h - __half2float(hh));
                    g_h0h[(size_t)t * HDIM + j0 + tid] = hh;
                    g_h0l[(size_t)t * HDIM + j0 + tid] = hl;
                }
                __syncwarp();                       // orders all warp-0 h stores
                if (lane == 0) red_release(c0);     // ONE release per CTA per step
            }
        }
    } else {
        // ================= Layer 1 chain =================
        u32 afA[3][4][4], afB[3][4][4];
        load_frags<3>(afA, wih1, j0, nrows, wid, gid, tg);
        load_frags<3>(afB, whh1, j0, nrows, wid, gid, tg);
        for (int r = tid; r < 80; r += NTHR) sb[r] = 0.f;
        __syncthreads();
        for (int lr = tid; lr < nrows; lr += NTHR) {
            int R = ((lr & 3) << 10) + j0 + (lr >> 2);
            sb[lr] = bih1[R] + bhh1[R];
        }
        __syncthreads();

        for (int t = 0; t < T_STEPS; ++t) {
            // Phase A: W_ih1 . h0[t]  (L0 runs ahead; off the h1 critical path)
            if (tid == 0) wait_ge(c0, (u64)NC0 * (u64)(t + 1));
            __syncthreads();
            float acc[3][4];
#pragma unroll
            for (int mt = 0; mt < 3; ++mt) {
#pragma unroll
                for (int i = 0; i < 4; ++i) acc[mt][i] = 0.f;
            }
            mma_phase<3>(acc, afA,
                         g_h0h + (size_t)t * HDIM,
                         g_h0l + (size_t)t * HDIM, wid, gid, tg);

            // Phase B: W_hh1 . h1[t-1]
            if (t > 0) {
                if (tid == 0) wait_ge(c1, (u64)NC1 * (u64)t);
                __syncthreads();
                mma_phase<3>(acc, afB,
                             g_h1h + (size_t)(t - 1) * HDIM,
                             g_h1l + (size_t)(t - 1) * HDIM, wid, gid, tg);
            }
            store_partials<3>(acc, sp, wid, gid, tg);
            __syncthreads();
            if (tid < 48) {
                float s = sb[tid];
#pragma unroll
                for (int w = 0; w < 16; ++w) s += sp[tid * 17 + w];
                sg[tid] = s;
            }
            __syncthreads();
            if (wid == 0) {
                if (tid < nj) {
                    float gi = sg[tid*4+0], gf = sg[tid*4+1];
                    float gc = sg[tid*4+2], go = sg[tid*4+3];
                    float i_ = fsig(gi), f_ = fsig(gf);
                    float ci = ftanh_(gc), o_ = fsig(go);
                    float cp = (t == 0) ? 0.f : sc[tid];
                    float c  = fmaf(f_, cp, i_ * ci);
                    sc[tid] = c;
                    float h = o_ * ftanh_(c);
                    __half hh = __float2half(h);
                    __half hl = __float2half(h - __half2float(hh));
                    g_h1h[(size_t)t * HDIM + j0 + tid] = hh;
                    g_h1l[(size_t)t * HDIM + j0 + tid] = hl;
                }
                __syncwarp();
                if (lane == 0) red_release(c1);
            }
        }

        // ---- Final linear (first L1 CTA) ----
        if (bid == NC0) {
            if (tid == 0) wait_ge(c1, (u64)NC1 * (u64)T_STEPS);
            __syncthreads();
            const __half* hh = g_h1h + (size_t)(T_STEPS - 1) * HDIM;
            const __half* hl = g_h1l + (size_t)(T_STEPS - 1) * HDIM;
            float p = 0.f;
            for (int k = tid; k < HDIM; k += NTHR) {
                p = fmaf(__half2float(hh[k]) + __half2float(hl[k]), wlin[k], p);
            }
#pragma unroll
            for (int off = 16; off; off >>= 1) {
                p += __shfl_xor_sync(0xffffffffu, p, off);
            }
            if (lane == 0) sred[wid] = p;
            __syncthreads();
            if (tid == 0) {
                float sres = blin[0];
#pragma unroll
                for (int w = 0; w < 16; ++w) sres += sred[w];
                out[0] = sres;
            }
        }
    }
}

extern "C" void kernel_launch(void* const* d_in, const int* in_sizes, int n_in,
                              void* d_out, int out_size)
{
    init_kernel<<<1, 32>>>();
    gx0_kernel<<<(T_STEPS * GDIM + 255) / 256, 256>>>(
        (const float*)d_in[0], (const float*)d_in[1],
        (const float*)d_in[3], (const float*)d_in[4]);
    lstm_kernel<<<NCTA, NTHR>>>(
        (const float*)d_in[2],                        // w_hh0
        (const float*)d_in[5], (const float*)d_in[6], // w_ih1, w_hh1
        (const float*)d_in[7], (const float*)d_in[8], // b_ih1, b_hh1
        (const float*)d_in[9], (const float*)d_in[10],
        (float*)d_out);
}